// round 9
// baseline (speedup 1.0000x reference)
#include <cuda_runtime.h>
#include <math.h>
#include <stdint.h>

// ---------------------------------------------------------------------------
// Shapes (fixed)
// ---------------------------------------------------------------------------
#define Hd 1024
#define Fd 4096
#define Ed 8
#define Td 512
#define OUT_TOK 2048

// ---------------------------------------------------------------------------
// Static device scratch (allocation-free per harness rules)
// ---------------------------------------------------------------------------
__device__ float g_buf [Ed * Td * Hd];                  // dispatched acts (tf32-rounded)
__device__ float g_hmid[(size_t)Ed * Td * Fd];          // GEMM1+GELU out (tf32-rounded)
__device__ float g_obuf[Ed * Td * Hd];                  // GEMM2 out (fp32)
__device__ int   g_order[Td][Ed];
__device__ float g_score[Td][Ed];

// ---------------------------------------------------------------------------
// Helpers
// ---------------------------------------------------------------------------
__device__ __forceinline__ uint32_t smem_u32(const void* p) {
    uint32_t a;
    asm("{ .reg .u64 t; cvta.to.shared.u64 t, %1; cvt.u32.u64 %0, t; }" : "=r"(a) : "l"(p));
    return a;
}
__device__ __forceinline__ float tf32r(float x) {
    uint32_t u;
    asm("cvt.rna.tf32.f32 %0, %1;" : "=r"(u) : "f"(x));
    return __uint_as_float(u);
}
__device__ __forceinline__ void cp_async16(uint32_t saddr, const void* gaddr) {
    asm volatile("cp.async.cg.shared.global [%0], [%1], 16;" :: "r"(saddr), "l"(gaddr));
}
__device__ __forceinline__ void cp_commit() {
    asm volatile("cp.async.commit_group;" ::: "memory");
}
__device__ __forceinline__ void cp_wait1() {
    asm volatile("cp.async.wait_group 1;" ::: "memory");
}
__device__ __forceinline__ void mma_tf32(float c[4], uint32_t a0, uint32_t a1,
                                         uint32_t a2, uint32_t a3,
                                         uint32_t b0, uint32_t b1) {
    asm volatile(
        "mma.sync.aligned.m16n8k8.row.col.f32.tf32.tf32.f32 "
        "{%0,%1,%2,%3}, {%4,%5,%6,%7}, {%8,%9}, {%0,%1,%2,%3};"
        : "+f"(c[0]), "+f"(c[1]), "+f"(c[2]), "+f"(c[3])
        : "r"(a0), "r"(a1), "r"(a2), "r"(a3), "r"(b0), "r"(b1));
}
__device__ __forceinline__ float gelu_exact(float v) {
    return 0.5f * v * (1.0f + erff(v * 0.70710678118654752f));
}

// ---------------------------------------------------------------------------
// Gating
// ---------------------------------------------------------------------------
__global__ void gate_kernel(const float* __restrict__ x,
                            const float* __restrict__ Wg,
                            const float* __restrict__ bg) {
    int warp = threadIdx.x >> 5;
    int lane = threadIdx.x & 31;
    int t = blockIdx.x * 8 + warp;
    if (t >= Td) return;

    const float* xr = x + (size_t)t * Hd;
    float acc[Ed];
#pragma unroll
    for (int e = 0; e < Ed; e++) acc[e] = 0.f;
    for (int h = lane; h < Hd; h += 32) {
        float xv = xr[h];
        const float* wr = Wg + (size_t)h * Ed;
#pragma unroll
        for (int e = 0; e < Ed; e++) acc[e] += xv * wr[e];
    }
#pragma unroll
    for (int e = 0; e < Ed; e++) {
#pragma unroll
        for (int o = 16; o > 0; o >>= 1)
            acc[e] += __shfl_xor_sync(0xffffffffu, acc[e], o);
    }
    if (lane == 0) {
        float l[Ed], p[Ed];
        float mx = -1e30f;
#pragma unroll
        for (int e = 0; e < Ed; e++) { l[e] = acc[e] + bg[e]; mx = fmaxf(mx, l[e]); }
        float s = 0.f;
#pragma unroll
        for (int e = 0; e < Ed; e++) { p[e] = expf(l[e] - mx); s += p[e]; }
#pragma unroll
        for (int e = 0; e < Ed; e++) p[e] /= s;
        float sum = 0.f;
#pragma unroll
        for (int e = 0; e < Ed; e++) sum += p[e];
        float inv = 1.0f / (sum + 1e-9f);
        bool used[Ed];
#pragma unroll
        for (int e = 0; e < Ed; e++) used[e] = false;
        for (int r = 0; r < Ed; r++) {
            int best = -1; float bv = -1e30f;
            for (int e = 0; e < Ed; e++)
                if (!used[e] && p[e] > bv) { bv = p[e]; best = e; }
            used[best] = true;
            g_order[t][r] = best;
            g_score[t][r] = bv * inv;
        }
    }
}

// ---------------------------------------------------------------------------
// Dispatch (tf32-rounds the MMA A operand)
// ---------------------------------------------------------------------------
__global__ void dispatch_kernel(const float* __restrict__ x) {
    int t = blockIdx.x;
    int r = blockIdx.y;
    int e = g_order[t][r];
    float sc = g_score[t][r];
    int src = 4 * t + (r >> 1);
    const float4* xs = (const float4*)(x + (size_t)src * Hd);
    float4* dst = (float4*)(g_buf + ((size_t)e * Td + t) * Hd);
    float4 v = xs[threadIdx.x];
    v.x = tf32r(v.x * sc); v.y = tf32r(v.y * sc);
    v.z = tf32r(v.z * sc); v.w = tf32r(v.w * sc);
    dst[threadIdx.x] = v;
}

// ---------------------------------------------------------------------------
// tf32 mma.sync GEMM, occupancy-optimized:
//   BM=64 BN=128 BK=16, 256 threads, 3 CTAs/SM (24 warps/SM).
//   Warp grid 2x4, each warp a 32x32 tile (2x4 m16n8k8 tiles, 32 acc regs).
//   A: 3-stage cp.async (proven R4 path). B: LDG->reg->STS transpose (proven).
//   SMEM row stride 20 -> conflict-free LDS/STS (proven R4 layout).
// ---------------------------------------------------------------------------
#define LDSSTR 20
#define AWORDS (64 * LDSSTR)                 // A words per stage
#define BWORDS (128 * LDSSTR)                // B words per stage
#define GEMM_SMEM_BYTES (3 * (AWORDS + BWORDS) * 4)   // 46080

template <int Kdim, int Ndim, bool DoGelu>
__global__ __launch_bounds__(256, 3)
void gemm_mma(const float* __restrict__ A_, const float* __restrict__ B_,
              const float* __restrict__ bias_, float* __restrict__ C_) {
    constexpr int BK = 16;
    constexpr int NK = Kdim / BK;

    extern __shared__ float smem[];
    float* AsBase = smem;                       // [3][64][20]
    float* BsBase = smem + 3 * AWORDS;          // [3][128 n][20 k]

    const int e  = blockIdx.z;
    const int m0 = blockIdx.y * 64;
    const int n0 = blockIdx.x * 128;
    const int tid = threadIdx.x;

    const float* Ag = A_ + (size_t)e * Td * Kdim;
    const float* Bg = B_ + (size_t)e * Kdim * Ndim;   // [K][N] row-major

    // ---- A loader (cp.async): thread -> one float4 of one row ----
    const int lrow = tid >> 2;                  // 0..63
    const int lcol = (tid & 3) * 4;             // 0,4,8,12
    const uint32_t sA0 = smem_u32(AsBase) + (uint32_t)(lrow * LDSSTR + lcol) * 4;
    const float* gA0 = Ag + (size_t)(m0 + lrow) * Kdim + lcol;

    auto cpA = [&](int i) {
        uint32_t sa = sA0 + (uint32_t)((i % 3) * AWORDS) * 4;
        cp_async16(sa, gA0 + i * BK);
        cp_commit();
    };

    // ---- B loader: thread covers column n_b, k-rows {4kq..} and {4kq+8..} ----
    const int n_b = tid & 127;
    const int kq  = tid >> 7;                   // 0..1
    const float* gB0 = Bg + (size_t)(kq * 4) * Ndim + n0 + n_b;
    float br[8];

    auto ldgB = [&](int i) {
        const float* p = gB0 + (size_t)(i * BK) * Ndim;
#pragma unroll
        for (int ii = 0; ii < 4; ii++) br[ii] = tf32r(p[(size_t)ii * Ndim]);
        const float* p2 = p + (size_t)8 * Ndim;
#pragma unroll
        for (int ii = 0; ii < 4; ii++) br[4 + ii] = tf32r(p2[(size_t)ii * Ndim]);
    };
    auto stsB = [&](int i) {
        float* bs = BsBase + (i % 3) * BWORDS + n_b * LDSSTR + kq * 4;
        *(float4*)(bs)     = *(const float4*)&br[0];
        *(float4*)(bs + 8) = *(const float4*)&br[4];
    };

    // ---- warp/fragment mapping: 2x4 warp grid, 32x32 warp tiles ----
    const int wid = tid >> 5;
    const int lane = tid & 31;
    const int wm = wid >> 2;                    // 0..1 (M)
    const int wn = wid & 3;                     // 0..3 (N)
    const int grp = lane >> 2;                  // 0..7
    const int tg  = lane & 3;                   // 0..3

    float c[2][4][4];
#pragma unroll
    for (int mt = 0; mt < 2; mt++)
#pragma unroll
        for (int nt = 0; nt < 4; nt++)
#pragma unroll
            for (int q = 0; q < 4; q++) c[mt][nt][q] = 0.f;

    // prologue
    ldgB(0); stsB(0);
    ldgB(1); stsB(1);
    cpA(0);  cpA(1);

    for (int i = 0; i < NK; i++) {
        cp_wait1();
        __syncthreads();
        if (i + 2 < NK) { ldgB(i + 2); cpA(i + 2); }
        else cp_commit();

        const uint32_t* as = (const uint32_t*)(AsBase + (i % 3) * AWORDS);
        const uint32_t* bs = (const uint32_t*)(BsBase + (i % 3) * BWORDS);

#pragma unroll
        for (int kk = 0; kk < 2; kk++) {
            const int kb = kk * 8 + tg;
            uint32_t a[2][4], b[4][2];
#pragma unroll
            for (int mt = 0; mt < 2; mt++) {
                int r = wm * 32 + mt * 16 + grp;
                a[mt][0] = as[r * LDSSTR + kb];
                a[mt][1] = as[(r + 8) * LDSSTR + kb];
                a[mt][2] = as[r * LDSSTR + kb + 4];
                a[mt][3] = as[(r + 8) * LDSSTR + kb + 4];
            }
#pragma unroll
            for (int nt = 0; nt < 4; nt++) {
                int cn = wn * 32 + nt * 8 + grp;
                b[nt][0] = bs[cn * LDSSTR + kb];
                b[nt][1] = bs[cn * LDSSTR + kb + 4];
            }
#pragma unroll
            for (int mt = 0; mt < 2; mt++)
#pragma unroll
                for (int nt = 0; nt < 4; nt++)
                    mma_tf32(c[mt][nt], a[mt][0], a[mt][1], a[mt][2], a[mt][3],
                             b[nt][0], b[nt][1]);
        }

        if (i + 2 < NK) stsB(i + 2);   // barrier at top of i+1 protects readers
    }

    // Epilogue: bias (+GELU +tf32 round), float2 stores
    const float* bias = bias_ + (size_t)e * Ndim + n0;
    float* C = C_ + (size_t)e * Td * Ndim;
#pragma unroll
    for (int mt = 0; mt < 2; mt++) {
        int r0 = m0 + wm * 32 + mt * 16 + grp;
#pragma unroll
        for (int nt = 0; nt < 4; nt++) {
            int col = wn * 32 + nt * 8 + tg * 2;
            float bx = bias[col], by = bias[col + 1];
            float2 v0, v1;
            v0.x = c[mt][nt][0] + bx;  v0.y = c[mt][nt][1] + by;
            v1.x = c[mt][nt][2] + bx;  v1.y = c[mt][nt][3] + by;
            if (DoGelu) {
                v0.x = tf32r(gelu_exact(v0.x)); v0.y = tf32r(gelu_exact(v0.y));
                v1.x = tf32r(gelu_exact(v1.x)); v1.y = tf32r(gelu_exact(v1.y));
            }
            *(float2*)(C + (size_t)r0 * Ndim + n0 + col) = v0;
            *(float2*)(C + (size_t)(r0 + 8) * Ndim + n0 + col) = v1;
        }
    }
}

// ---------------------------------------------------------------------------
// Combine
// ---------------------------------------------------------------------------
__global__ void combine_kernel(float* __restrict__ out) {
    int m = blockIdx.x;
    int t = m >> 2;
    int q = m & 3;
    int e1 = g_order[t][2 * q];
    int e2 = g_order[t][2 * q + 1];
    const float4* o1 = (const float4*)(g_obuf + ((size_t)e1 * Td + t) * Hd);
    const float4* o2 = (const float4*)(g_obuf + ((size_t)e2 * Td + t) * Hd);
    float4* dst = (float4*)(out + (size_t)m * Hd);
    float4 a = o1[threadIdx.x];
    float4 b = o2[threadIdx.x];
    float4 v; v.x = a.x + b.x; v.y = a.y + b.y; v.z = a.z + b.z; v.w = a.w + b.w;
    dst[threadIdx.x] = v;
}

// ---------------------------------------------------------------------------
extern "C" void kernel_launch(void* const* d_in, const int* in_sizes, int n_in,
                              void* d_out, int out_size) {
    (void)in_sizes; (void)n_in;
    const float* x  = (const float*)d_in[0];
    const float* Wg = (const float*)d_in[1];
    const float* bg = (const float*)d_in[2];
    const float* W1 = (const float*)d_in[3];
    const float* b1 = (const float*)d_in[4];
    const float* W2 = (const float*)d_in[5];
    const float* b2 = (const float*)d_in[6];
    float* out = (float*)d_out;

    float *buf, *hmid, *obuf;
    cudaGetSymbolAddress((void**)&buf,  g_buf);
    cudaGetSymbolAddress((void**)&hmid, g_hmid);
    cudaGetSymbolAddress((void**)&obuf, g_obuf);

    cudaFuncSetAttribute(gemm_mma<Hd, Fd, true>,
                         cudaFuncAttributeMaxDynamicSharedMemorySize, GEMM_SMEM_BYTES);
    cudaFuncSetAttribute(gemm_mma<Fd, Hd, false>,
                         cudaFuncAttributeMaxDynamicSharedMemorySize, GEMM_SMEM_BYTES);

    // Output tail (batches 1-3 + aux-loss scalar, all exactly zero)
    size_t nz = (size_t)OUT_TOK * Hd;
    cudaMemsetAsync(out + nz, 0, ((size_t)out_size - nz) * sizeof(float), 0);

    gate_kernel<<<Td / 8, 256>>>(x, Wg, bg);
    dispatch_kernel<<<dim3(Td, Ed), 256>>>(x);

    // GEMM1 + GELU: per expert (512 x 1024) @ (1024 x 4096)
    gemm_mma<Hd, Fd, true><<<dim3(Fd / 128, Td / 64, Ed), 256, GEMM_SMEM_BYTES>>>(buf, W1, b1, hmid);
    // GEMM2: per expert (512 x 4096) @ (4096 x 1024)
    gemm_mma<Fd, Hd, false><<<dim3(Hd / 128, Td / 64, Ed), 256, GEMM_SMEM_BYTES>>>(hmid, W2, b2, obuf);

    combine_kernel<<<OUT_TOK, 256>>>(out);
}

// round 10
// speedup vs baseline: 1.3138x; 1.3138x over previous
#include <cuda_runtime.h>
#include <math.h>
#include <stdint.h>

// ---------------------------------------------------------------------------
// Shapes (fixed)
// ---------------------------------------------------------------------------
#define Hd 1024
#define Fd 4096
#define Ed 8
#define Td 512
#define OUT_TOK 2048

// ---------------------------------------------------------------------------
// Static device scratch (allocation-free per harness rules)
// ---------------------------------------------------------------------------
__device__ float g_buf [Ed * Td * Hd];                  // dispatched acts (tf32-rounded)
__device__ float g_hmid[(size_t)Ed * Td * Fd];          // GEMM1+GELU out (tf32-rounded)
__device__ float g_obuf[Ed * Td * Hd];                  // GEMM2 out (fp32)
__device__ int   g_order[Td][Ed];
__device__ float g_score[Td][Ed];

// ---------------------------------------------------------------------------
// Helpers
// ---------------------------------------------------------------------------
__device__ __forceinline__ uint32_t smem_u32(const void* p) {
    uint32_t a;
    asm("{ .reg .u64 t; cvta.to.shared.u64 t, %1; cvt.u32.u64 %0, t; }" : "=r"(a) : "l"(p));
    return a;
}
__device__ __forceinline__ float tf32r(float x) {
    uint32_t u;
    asm("cvt.rna.tf32.f32 %0, %1;" : "=r"(u) : "f"(x));
    return __uint_as_float(u);
}
__device__ __forceinline__ void cp_async16(uint32_t saddr, const void* gaddr) {
    asm volatile("cp.async.cg.shared.global [%0], [%1], 16;" :: "r"(saddr), "l"(gaddr));
}
__device__ __forceinline__ void cp_commit() {
    asm volatile("cp.async.commit_group;" ::: "memory");
}
__device__ __forceinline__ void cp_wait1() {
    asm volatile("cp.async.wait_group 1;" ::: "memory");
}
__device__ __forceinline__ void ldsm_x4(uint32_t& r0, uint32_t& r1, uint32_t& r2,
                                        uint32_t& r3, uint32_t addr) {
    asm volatile("ldmatrix.sync.aligned.m8n8.x4.shared.b16 {%0,%1,%2,%3}, [%4];"
                 : "=r"(r0), "=r"(r1), "=r"(r2), "=r"(r3) : "r"(addr));
}
__device__ __forceinline__ void mma_tf32(float c[4], uint32_t a0, uint32_t a1,
                                         uint32_t a2, uint32_t a3,
                                         uint32_t b0, uint32_t b1) {
    asm volatile(
        "mma.sync.aligned.m16n8k8.row.col.f32.tf32.tf32.f32 "
        "{%0,%1,%2,%3}, {%4,%5,%6,%7}, {%8,%9}, {%0,%1,%2,%3};"
        : "+f"(c[0]), "+f"(c[1]), "+f"(c[2]), "+f"(c[3])
        : "r"(a0), "r"(a1), "r"(a2), "r"(a3), "r"(b0), "r"(b1));
}
__device__ __forceinline__ float gelu_exact(float v) {
    return 0.5f * v * (1.0f + erff(v * 0.70710678118654752f));
}

// ---------------------------------------------------------------------------
// Gating
// ---------------------------------------------------------------------------
__global__ void gate_kernel(const float* __restrict__ x,
                            const float* __restrict__ Wg,
                            const float* __restrict__ bg) {
    int warp = threadIdx.x >> 5;
    int lane = threadIdx.x & 31;
    int t = blockIdx.x * 8 + warp;
    if (t >= Td) return;

    const float* xr = x + (size_t)t * Hd;
    float acc[Ed];
#pragma unroll
    for (int e = 0; e < Ed; e++) acc[e] = 0.f;
    for (int h = lane; h < Hd; h += 32) {
        float xv = xr[h];
        const float* wr = Wg + (size_t)h * Ed;
#pragma unroll
        for (int e = 0; e < Ed; e++) acc[e] += xv * wr[e];
    }
#pragma unroll
    for (int e = 0; e < Ed; e++) {
#pragma unroll
        for (int o = 16; o > 0; o >>= 1)
            acc[e] += __shfl_xor_sync(0xffffffffu, acc[e], o);
    }
    if (lane == 0) {
        float l[Ed], p[Ed];
        float mx = -1e30f;
#pragma unroll
        for (int e = 0; e < Ed; e++) { l[e] = acc[e] + bg[e]; mx = fmaxf(mx, l[e]); }
        float s = 0.f;
#pragma unroll
        for (int e = 0; e < Ed; e++) { p[e] = expf(l[e] - mx); s += p[e]; }
#pragma unroll
        for (int e = 0; e < Ed; e++) p[e] /= s;
        float sum = 0.f;
#pragma unroll
        for (int e = 0; e < Ed; e++) sum += p[e];
        float inv = 1.0f / (sum + 1e-9f);
        bool used[Ed];
#pragma unroll
        for (int e = 0; e < Ed; e++) used[e] = false;
        for (int r = 0; r < Ed; r++) {
            int best = -1; float bv = -1e30f;
            for (int e = 0; e < Ed; e++)
                if (!used[e] && p[e] > bv) { bv = p[e]; best = e; }
            used[best] = true;
            g_order[t][r] = best;
            g_score[t][r] = bv * inv;
        }
    }
}

// ---------------------------------------------------------------------------
// Dispatch (tf32-rounds the MMA A operand)
// ---------------------------------------------------------------------------
__global__ void dispatch_kernel(const float* __restrict__ x) {
    int t = blockIdx.x;
    int r = blockIdx.y;
    int e = g_order[t][r];
    float sc = g_score[t][r];
    int src = 4 * t + (r >> 1);
    const float4* xs = (const float4*)(x + (size_t)src * Hd);
    float4* dst = (float4*)(g_buf + ((size_t)e * Td + t) * Hd);
    float4 v = xs[threadIdx.x];
    v.x = tf32r(v.x * sc); v.y = tf32r(v.y * sc);
    v.z = tf32r(v.z * sc); v.w = tf32r(v.w * sc);
    dst[threadIdx.x] = v;
}

// ---------------------------------------------------------------------------
// tf32 mma.sync GEMM (R4 structure) + ldmatrix fragment loads.
//   BM=128 BN=128 BK=16, 256 threads, 2 CTAs/SM.
//   A: 3-stage cp.async (k-contiguous rows, stride 20).
//   B: LDG->reg->STS transpose (original [K][N] layout), stride 20.
//   Fragments: ldmatrix.x4.b16 (4 A-ops + 2 B-ops per kk) -> 12 LDSM/iter
//   instead of 48 LDS.32. Lane-address sets verified conflict-free.
// ---------------------------------------------------------------------------
#define LDSSTR 20
#define TILE_WORDS (128 * LDSSTR)          // per-operand per-stage words
#define GEMM_SMEM_BYTES (2 * 3 * TILE_WORDS * 4)   // 61440

template <int Kdim, int Ndim, bool DoGelu>
__global__ __launch_bounds__(256, 2)
void gemm_mma(const float* __restrict__ A_, const float* __restrict__ B_,
              const float* __restrict__ bias_, float* __restrict__ C_) {
    constexpr int BK = 16;
    constexpr int NK = Kdim / BK;

    extern __shared__ float smem[];
    float* AsBase = smem;                       // [3][128 row][20]
    float* BsBase = smem + 3 * TILE_WORDS;      // [3][128 n][20 k]

    const int e  = blockIdx.z;
    const int m0 = blockIdx.y * 128;
    const int n0 = blockIdx.x * 128;
    const int tid = threadIdx.x;

    const float* Ag = A_ + (size_t)e * Td * Kdim;
    const float* Bg = B_ + (size_t)e * Kdim * Ndim;   // [K][N] row-major

    // ---- A loader (cp.async, K-major already) ----
    const int lrow = tid >> 1;                  // 0..127
    const int lcol = (tid & 1) * 8;             // 0 or 8
    const uint32_t sA0 = smem_u32(AsBase) + (uint32_t)(lrow * LDSSTR + lcol) * 4;
    const float* gA0 = Ag + (size_t)(m0 + lrow) * Kdim + lcol;

    auto cpA = [&](int i) {
        uint32_t sa = sA0 + (uint32_t)((i % 3) * TILE_WORDS) * 4;
        const float* ga = gA0 + i * BK;
        cp_async16(sa, ga);
        cp_async16(sa + 16, ga + 4);
        cp_commit();
    };

    // ---- B loader: thread covers column n_b, k-rows {4kq..} and {4kq+8..} ----
    const int n_b = tid & 127;
    const int kq  = tid >> 7;                   // 0..1
    const float* gB0 = Bg + (size_t)(kq * 4) * Ndim + n0 + n_b;
    float br[8];

    auto ldgB = [&](int i) {
        const float* p = gB0 + (size_t)(i * BK) * Ndim;
#pragma unroll
        for (int ii = 0; ii < 4; ii++) br[ii] = tf32r(p[(size_t)ii * Ndim]);
        const float* p2 = p + (size_t)8 * Ndim;
#pragma unroll
        for (int ii = 0; ii < 4; ii++) br[4 + ii] = tf32r(p2[(size_t)ii * Ndim]);
    };
    auto stsB = [&](int i) {
        float* bs = BsBase + (i % 3) * TILE_WORDS + n_b * LDSSTR + kq * 4;
        *(float4*)(bs)     = *(const float4*)&br[0];
        *(float4*)(bs + 8) = *(const float4*)&br[4];
    };

    // ---- warp/fragment mapping ----
    const int wid = tid >> 5;
    const int lane = tid & 31;
    const int wm = wid >> 2;                    // 0..1
    const int wn = wid & 3;                     // 0..3
    const int grp = lane >> 2;                  // 0..7
    const int tg  = lane & 3;                   // 0..3

    // ldmatrix lane-address bases (32-bit SMEM addresses, byte units).
    // A x4 per (mt,kk): m0 rows r..r+7 @k0 | m1 rows r+8..r+15 @k0
    //                   m2 rows r..r+7 @k0+4 | m3 rows r+8..r+15 @k0+4
    //   lane row = wm*64 + (lane&15);  lane col = ((lane>>4)<<2)
    const uint32_t aLdsmBase = smem_u32(AsBase) +
        (uint32_t)(((wm * 64 + (lane & 15)) * LDSSTR + ((lane >> 4) << 2)) * 4);
    // B x4 per (pair q, kk): m0 rows cn..cn+7 @k0 | m1 same rows @k0+4
    //                        m2 rows cn+8..cn+15 @k0 | m3 @k0+4
    //   lane row = wn*32 + ((lane>>4)<<3) + (lane&7); col = ((lane>>3)&1)<<2
    const uint32_t bLdsmBase = smem_u32(BsBase) +
        (uint32_t)(((wn * 32 + ((lane >> 4) << 3) + (lane & 7)) * LDSSTR +
                    (((lane >> 3) & 1) << 2)) * 4);

    float c[4][4][4];
#pragma unroll
    for (int mt = 0; mt < 4; mt++)
#pragma unroll
        for (int nt = 0; nt < 4; nt++)
#pragma unroll
            for (int q = 0; q < 4; q++) c[mt][nt][q] = 0.f;

    // prologue: stages 0 and 1
    ldgB(0); stsB(0);
    ldgB(1); stsB(1);
    cpA(0);  cpA(1);

    for (int i = 0; i < NK; i++) {
        cp_wait1();
        __syncthreads();
        if (i + 2 < NK) { ldgB(i + 2); cpA(i + 2); }
        else cp_commit();

        const uint32_t stA = aLdsmBase + (uint32_t)((i % 3) * TILE_WORDS) * 4;
        const uint32_t stB = bLdsmBase + (uint32_t)((i % 3) * TILE_WORDS) * 4;

#pragma unroll
        for (int kk = 0; kk < 2; kk++) {
            const uint32_t koff = (uint32_t)(kk * 8) * 4;
            uint32_t a[4][4], b[4][2];
            // B: 2 x4 ops cover nt pairs (0,1) and (2,3)
#pragma unroll
            for (int q = 0; q < 2; q++) {
                uint32_t addr = stB + koff + (uint32_t)(q * 16 * LDSSTR) * 4;
                ldsm_x4(b[2 * q][0], b[2 * q][1], b[2 * q + 1][0], b[2 * q + 1][1], addr);
            }
            // A: 4 x4 ops, one per mt
#pragma unroll
            for (int mt = 0; mt < 4; mt++) {
                uint32_t addr = stA + koff + (uint32_t)(mt * 16 * LDSSTR) * 4;
                ldsm_x4(a[mt][0], a[mt][1], a[mt][2], a[mt][3], addr);
            }
#pragma unroll
            for (int mt = 0; mt < 4; mt++)
#pragma unroll
                for (int nt = 0; nt < 4; nt++)
                    mma_tf32(c[mt][nt], a[mt][0], a[mt][1], a[mt][2], a[mt][3],
                             b[nt][0], b[nt][1]);
        }

        if (i + 2 < NK) stsB(i + 2);   // barrier at next-iter top protects readers
    }

    // Epilogue: bias (+GELU +tf32 round), float2 stores
    const float* bias = bias_ + (size_t)e * Ndim + n0;
    float* C = C_ + (size_t)e * Td * Ndim;
#pragma unroll
    for (int mt = 0; mt < 4; mt++) {
        int r0 = m0 + wm * 64 + mt * 16 + grp;
#pragma unroll
        for (int nt = 0; nt < 4; nt++) {
            int col = wn * 32 + nt * 8 + tg * 2;
            float bx = bias[col], by = bias[col + 1];
            float2 v0, v1;
            v0.x = c[mt][nt][0] + bx;  v0.y = c[mt][nt][1] + by;
            v1.x = c[mt][nt][2] + bx;  v1.y = c[mt][nt][3] + by;
            if (DoGelu) {
                v0.x = tf32r(gelu_exact(v0.x)); v0.y = tf32r(gelu_exact(v0.y));
                v1.x = tf32r(gelu_exact(v1.x)); v1.y = tf32r(gelu_exact(v1.y));
            }
            *(float2*)(C + (size_t)r0 * Ndim + n0 + col) = v0;
            *(float2*)(C + (size_t)(r0 + 8) * Ndim + n0 + col) = v1;
        }
    }
}

// ---------------------------------------------------------------------------
// Combine
// ---------------------------------------------------------------------------
__global__ void combine_kernel(float* __restrict__ out) {
    int m = blockIdx.x;
    int t = m >> 2;
    int q = m & 3;
    int e1 = g_order[t][2 * q];
    int e2 = g_order[t][2 * q + 1];
    const float4* o1 = (const float4*)(g_obuf + ((size_t)e1 * Td + t) * Hd);
    const float4* o2 = (const float4*)(g_obuf + ((size_t)e2 * Td + t) * Hd);
    float4* dst = (float4*)(out + (size_t)m * Hd);
    float4 a = o1[threadIdx.x];
    float4 b = o2[threadIdx.x];
    float4 v; v.x = a.x + b.x; v.y = a.y + b.y; v.z = a.z + b.z; v.w = a.w + b.w;
    dst[threadIdx.x] = v;
}

// ---------------------------------------------------------------------------
extern "C" void kernel_launch(void* const* d_in, const int* in_sizes, int n_in,
                              void* d_out, int out_size) {
    (void)in_sizes; (void)n_in;
    const float* x  = (const float*)d_in[0];
    const float* Wg = (const float*)d_in[1];
    const float* bg = (const float*)d_in[2];
    const float* W1 = (const float*)d_in[3];
    const float* b1 = (const float*)d_in[4];
    const float* W2 = (const float*)d_in[5];
    const float* b2 = (const float*)d_in[6];
    float* out = (float*)d_out;

    float *buf, *hmid, *obuf;
    cudaGetSymbolAddress((void**)&buf,  g_buf);
    cudaGetSymbolAddress((void**)&hmid, g_hmid);
    cudaGetSymbolAddress((void**)&obuf, g_obuf);

    cudaFuncSetAttribute(gemm_mma<Hd, Fd, true>,
                         cudaFuncAttributeMaxDynamicSharedMemorySize, GEMM_SMEM_BYTES);
    cudaFuncSetAttribute(gemm_mma<Fd, Hd, false>,
                         cudaFuncAttributeMaxDynamicSharedMemorySize, GEMM_SMEM_BYTES);

    // Output tail (batches 1-3 + aux-loss scalar, all exactly zero)
    size_t nz = (size_t)OUT_TOK * Hd;
    cudaMemsetAsync(out + nz, 0, ((size_t)out_size - nz) * sizeof(float), 0);

    gate_kernel<<<Td / 8, 256>>>(x, Wg, bg);
    dispatch_kernel<<<dim3(Td, Ed), 256>>>(x);

    // GEMM1 + GELU: per expert (512 x 1024) @ (1024 x 4096), B in native layout
    gemm_mma<Hd, Fd, true><<<dim3(Fd / 128, Td / 128, Ed), 256, GEMM_SMEM_BYTES>>>(buf, W1, b1, hmid);
    // GEMM2: per expert (512 x 4096) @ (4096 x 1024), B in native layout
    gemm_mma<Fd, Hd, false><<<dim3(Hd / 128, Td / 128, Ed), 256, GEMM_SMEM_BYTES>>>(hmid, W2, b2, obuf);

    combine_kernel<<<OUT_TOK, 256>>>(out);
}